// round 13
// baseline (speedup 1.0000x reference)
#include <cuda_runtime.h>

namespace {
constexpr int NN   = 24;
constexpr int FIN  = 7;
constexpr int WD   = 64;
constexpr int FOUT = 13;
constexpr int TB   = 10;   // batch tile per CTA (single-buffered)
constexpr int HB   = 5;    // batch rows per thread (TB/2)
constexpr int NT   = 768;  // 24 nodes x 32 lanes (2 bq x 16 og); warp = node
constexpr int STATE = NN * WD;
}

// SMPL tree adjacency CSR (self + parent + children)
__constant__ int c_nbr_off[25] = {0,4,7,10,13,16,19,22,25,28,33,35,37,40,43,46,48,51,54,57,60,63,66,68,70};
__constant__ int c_nbr_lst[70] = {
    0,1,2,3, 1,0,4, 2,0,5, 3,0,6, 4,1,7, 5,2,8, 6,3,9, 7,4,10, 8,5,11,
    9,6,12,13,14, 10,7, 11,8, 12,9,15, 13,9,16, 14,9,17, 15,12, 16,13,18,
    17,14,19, 18,16,20, 19,17,21, 20,18,22, 21,19,23, 22,20, 23,21
};
__constant__ int c_nbr_m[70] = {
    0,0,0,0, 1,1,1, 2,2,2, 3,3,3, 4,4,4, 5,5,5, 6,6,6, 7,7,7, 8,8,8,
    9,9,9,9,9, 10,10, 11,11, 12,12,12, 13,13,13, 14,14,14, 15,15, 16,16,16,
    17,17,17, 18,18,18, 19,19,19, 20,20,20, 21,21,21, 22,22, 23,23
};

// packed 2xfp32 helpers (Blackwell f32x2; PTX-only)
__device__ __forceinline__ unsigned long long dup2(float s) {
    unsigned long long d;
    asm("mov.b64 %0, {%1, %1};" : "=l"(d) : "r"(__float_as_uint(s)));
    return d;
}
__device__ __forceinline__ void fma2(unsigned long long& d,
                                     unsigned long long a, unsigned long long b) {
    asm("fma.rn.f32x2 %0, %1, %2, %0;" : "+l"(d) : "l"(a), "l"(b));
}

__global__ __launch_bounds__(NT, 2)
void gnn_fused(const float* __restrict__ x,
               const float* __restrict__ w0, const float* __restrict__ w1,
               const float* __restrict__ w2, const float* __restrict__ w3,
               const float* __restrict__ aw0, const float* __restrict__ aw1,
               const float* __restrict__ aw2, const float* __restrict__ aw3,
               const float* __restrict__ b0, const float* __restrict__ b1,
               const float* __restrict__ b2, const float* __restrict__ b3,
               float* __restrict__ out, int B)
{
    extern __shared__ float smem[];
    float* S    = smem;                 // TB*STATE (single state buffer; head reused for L3 out)
    float* xin  = S + TB * STATE;       // TB*NN*FIN
    float* aeff = xin + TB * NN * FIN;  // 4*70
    float* bias = aeff + 4 * 70;        // 3*64 + 13

    const int tid = threadIdx.x;
    const long brow0 = (long)blockIdx.x * TB;

    // ---- stage constants + masked input ----
    for (int idx = tid; idx < 4 * 70; idx += NT) {
        int l = idx / 70, e = idx - l * 70;
        const float* aw = (l == 0) ? aw0 : (l == 1) ? aw1 : (l == 2) ? aw2 : aw3;
        aeff[idx] = aw[c_nbr_m[e] * NN + c_nbr_lst[e]];
    }
    for (int idx = tid; idx < 3 * WD + FOUT; idx += NT) {
        float v;
        if      (idx <     WD) v = b0[idx];
        else if (idx < 2 * WD) v = b1[idx - WD];
        else if (idx < 3 * WD) v = b2[idx - 2 * WD];
        else                   v = b3[idx - 3 * WD];
        bias[idx] = v;
    }
    for (int idx = tid; idx < TB * NN * FIN; idx += NT) {
        const int bl = idx / (NN * FIN);
        const int j  = idx % (NN * FIN);
        float v = 0.0f;
        if (brow0 + bl < B && j >= FIN)   // root joint masked
            v = x[(brow0 + bl) * (NN * FIN) + j];
        xin[idx] = v;
    }
    __syncthreads();

    // Thread map: warp = one node; lanes = 2 batch-groups x 16 o-groups.
    const int n    = tid >> 5;            // node 0..23
    const int lane = tid & 31;
    const int bq   = lane >> 4;           // batch group 0/1
    const int o0   = (lane & 15) * 4;     // output feature group
    const int bb   = bq * HB;             // first batch row for this thread

    // ---- Layer 0 matmul: xin @ w0 -> S ----
    {
        float4 acc[HB];
        #pragma unroll
        for (int b = 0; b < HB; b++) acc[b] = make_float4(0.f, 0.f, 0.f, 0.f);
        #pragma unroll
        for (int i = 0; i < FIN; i++) {
            const float4 wv = __ldg(reinterpret_cast<const float4*>(w0 + (n * FIN + i) * WD + o0));
            #pragma unroll
            for (int b = 0; b < HB; b++) {
                const float xv = xin[(bb + b) * (NN * FIN) + n * FIN + i];
                acc[b].x = fmaf(xv, wv.x, acc[b].x);
                acc[b].y = fmaf(xv, wv.y, acc[b].y);
                acc[b].z = fmaf(xv, wv.z, acc[b].z);
                acc[b].w = fmaf(xv, wv.w, acc[b].w);
            }
        }
        #pragma unroll
        for (int b = 0; b < HB; b++)
            *reinterpret_cast<float4*>(S + (bb + b) * STATE + n * WD + o0) = acc[b];
    }
    __syncthreads();

    // ---- In-place sparse tree aggregation + bias + ReLU on S ----
    // Local-pair schedule: the two bq groups touch disjoint batch rows, so the
    // only hazard is within a local pair; barrier separates reads from writes.
    auto agg = [&](const float* __restrict__ ae, const float* __restrict__ bi) {
        const int s = c_nbr_off[n], e = c_nbr_off[n + 1];
        const float4 bv = make_float4(bi[o0], bi[o0 + 1], bi[o0 + 2], bi[o0 + 3]);
        #pragma unroll
        for (int lp = 0; lp < HB; lp += 2) {
            const int cnt = (lp + 2 <= HB) ? 2 : 1;
            float4 a[2];
            a[0] = bv; a[1] = bv;
            for (int k = s; k < e; k++) {
                const float aw = ae[k];
                const float* hp = S + c_nbr_lst[k] * WD + o0;
                #pragma unroll
                for (int q = 0; q < 2; q++) {
                    if (q < cnt) {
                        const float4 h = *reinterpret_cast<const float4*>(hp + (bb + lp + q) * STATE);
                        a[q].x = fmaf(aw, h.x, a[q].x);
                        a[q].y = fmaf(aw, h.y, a[q].y);
                        a[q].z = fmaf(aw, h.z, a[q].z);
                        a[q].w = fmaf(aw, h.w, a[q].w);
                    }
                }
            }
            __syncthreads();   // all reads of this local pair done CTA-wide
            float* dp = S + n * WD + o0;
            #pragma unroll
            for (int q = 0; q < 2; q++) {
                if (q < cnt) {
                    a[q].x = fmaxf(a[q].x, 0.f); a[q].y = fmaxf(a[q].y, 0.f);
                    a[q].z = fmaxf(a[q].z, 0.f); a[q].w = fmaxf(a[q].w, 0.f);
                    *reinterpret_cast<float4*>(dp + (bb + lp + q) * STATE) = a[q];
                }
            }
            __syncthreads();   // writes visible before next pair's reads
        }
    };

    // ---- In-place hidden matmul (node-local), f32x2, i-step 2 (42-reg budget) ----
    auto mm64 = [&](const float* __restrict__ wgt) {
        unsigned long long accL[HB], accH[HB];
        #pragma unroll
        for (int b = 0; b < HB; b++) { accL[b] = 0ull; accH[b] = 0ull; }
        const float* wrow = wgt + n * WD * WD + o0;
        const float* abase = S + n * WD;
        #pragma unroll 4
        for (int i = 0; i < WD; i += 2) {
            const ulonglong2 wp0 = __ldg(reinterpret_cast<const ulonglong2*>(wrow + (i + 0) * WD));
            const ulonglong2 wp1 = __ldg(reinterpret_cast<const ulonglong2*>(wrow + (i + 1) * WD));
            #pragma unroll
            for (int b = 0; b < HB; b++) {
                const float2 xv = *reinterpret_cast<const float2*>(abase + (bb + b) * STATE + i);
                const unsigned long long x0 = dup2(xv.x);
                fma2(accL[b], x0, wp0.x);
                fma2(accH[b], x0, wp0.y);
                const unsigned long long x1 = dup2(xv.y);
                fma2(accL[b], x1, wp1.x);
                fma2(accH[b], x1, wp1.y);
            }
        }
        __syncthreads();   // all reads of S complete CTA-wide
        #pragma unroll
        for (int b = 0; b < HB; b++)
            *reinterpret_cast<ulonglong2*>(S + (bb + b) * STATE + n * WD + o0) =
                make_ulonglong2(accL[b], accH[b]);
        __syncthreads();
    };

    agg(aeff + 0,   bias + 0);        // L0 agg (+relu)
    mm64(w1);                          // L1 matmul
    agg(aeff + 70,  bias + WD);       // L1 agg (+relu)
    mm64(w2);                          // L2 matmul
    agg(aeff + 140, bias + 2 * WD);   // L2 agg (+relu)

    // ---- Layer 3 matmul: S @ w3 -> regs; then write into S head ----
    // 624 active threads: (n3, o3) x 2 batch halves.
    float acc3[HB];
    int n3 = 0, o3 = 0, bh3 = 0;
    const bool l3act = (tid < 2 * NN * FOUT);
    if (l3act) {
        bh3 = tid & 1;
        const int t = tid >> 1;
        n3 = t / FOUT; o3 = t - n3 * FOUT;
        #pragma unroll
        for (int b = 0; b < HB; b++) acc3[b] = 0.f;
        const int bb3 = bh3 * HB;
        #pragma unroll 4
        for (int i = 0; i < WD; i++) {
            const float wv = __ldg(w3 + (n3 * WD + i) * FOUT + o3);
            #pragma unroll
            for (int b = 0; b < HB; b++)
                acc3[b] = fmaf(S[(bb3 + b) * STATE + n3 * WD + i], wv, acc3[b]);
        }
    }
    __syncthreads();   // all reads of S done before head overwrite
    if (l3act) {
        const int bb3 = bh3 * HB;
        #pragma unroll
        for (int b = 0; b < HB; b++)
            S[(bb3 + b) * (NN * FOUT) + n3 * FOUT + o3] = acc3[b];
    }
    __syncthreads();

    // ---- Layer 3 aggregation + bias, store to global (guarded) ----
    if (l3act) {
        const int bb3 = bh3 * HB;
        const int s = c_nbr_off[n3], e = c_nbr_off[n3 + 1];
        const float bv3 = bias[3 * WD + o3];
        #pragma unroll
        for (int b = 0; b < HB; b++) {
            float a0 = bv3;
            for (int k = s; k < e; k++)
                a0 = fmaf(aeff[210 + k], S[(bb3 + b) * (NN * FOUT) + c_nbr_lst[k] * FOUT + o3], a0);
            if (brow0 + bb3 + b < B)
                out[(brow0 + bb3 + b) * (NN * FOUT) + n3 * FOUT + o3] = a0;
        }
    }
}

extern "C" void kernel_launch(void* const* d_in, const int* in_sizes, int n_in,
                              void* d_out, int out_size) {
    const float* x   = (const float*)d_in[0];
    const float* w0  = (const float*)d_in[1];
    const float* w1  = (const float*)d_in[2];
    const float* w2  = (const float*)d_in[3];
    const float* w3  = (const float*)d_in[4];
    const float* aw0 = (const float*)d_in[5];
    const float* aw1 = (const float*)d_in[6];
    const float* aw2 = (const float*)d_in[7];
    const float* aw3 = (const float*)d_in[8];
    const float* b0  = (const float*)d_in[9];
    const float* b1  = (const float*)d_in[10];
    const float* b2  = (const float*)d_in[11];
    const float* b3  = (const float*)d_in[12];
    float* out = (float*)d_out;

    const int B = in_sizes[0] / (NN * FIN);
    const int grid = (B + TB - 1) / TB;
    const size_t smem_bytes =
        (size_t)(TB * STATE + TB * NN * FIN + 4 * 70 + 3 * WD + FOUT) * sizeof(float);

    cudaFuncSetAttribute(gnn_fused, cudaFuncAttributeMaxDynamicSharedMemorySize,
                         (int)smem_bytes);
    gnn_fused<<<grid, NT, smem_bytes>>>(x, w0, w1, w2, w3,
                                        aw0, aw1, aw2, aw3,
                                        b0, b1, b2, b3, out, B);
}

// round 14
// speedup vs baseline: 2.1826x; 2.1826x over previous
#include <cuda_runtime.h>

namespace {
constexpr int NN   = 24;
constexpr int FIN  = 7;
constexpr int WD   = 64;
constexpr int FOUT = 13;
constexpr int TB   = 8;    // batch rows per CTA: two halves of 4
constexpr int NT   = 384;  // 24 nodes x 16 lanes
constexpr int ROWS_S = NN * WD;     // 1536 rows of 4 floats per half
constexpr int HALF   = 4 * (ROWS_S + ROWS_S / 4);   // 7680 floats
constexpr int ROWS_X = NN * FIN;    // 168
constexpr int XHALF  = 4 * (ROWS_X + (ROWS_X + 3) / 4);  // 840
}

// padded row offset: row r -> float offset 4*(r + r/4); always 16B aligned,
// spreads o-strided lane rows across bank quads.
__device__ __forceinline__ int rofs(int r) { return 4 * (r + (r >> 2)); }

// SMPL tree adjacency CSR (self + parent + children)
__constant__ int c_nbr_off[25] = {0,4,7,10,13,16,19,22,25,28,33,35,37,40,43,46,48,51,54,57,60,63,66,68,70};
__constant__ int c_nbr_lst[70] = {
    0,1,2,3, 1,0,4, 2,0,5, 3,0,6, 4,1,7, 5,2,8, 6,3,9, 7,4,10, 8,5,11,
    9,6,12,13,14, 10,7, 11,8, 12,9,15, 13,9,16, 14,9,17, 15,12, 16,13,18,
    17,14,19, 18,16,20, 19,17,21, 20,18,22, 21,19,23, 22,20, 23,21
};
__constant__ int c_nbr_m[70] = {
    0,0,0,0, 1,1,1, 2,2,2, 3,3,3, 4,4,4, 5,5,5, 6,6,6, 7,7,7, 8,8,8,
    9,9,9,9,9, 10,10, 11,11, 12,12,12, 13,13,13, 14,14,14, 15,15, 16,16,16,
    17,17,17, 18,18,18, 19,19,19, 20,20,20, 21,21,21, 22,22, 23,23
};

// packed 2xfp32 helpers (Blackwell f32x2; PTX-only)
__device__ __forceinline__ unsigned long long dup2(float s) {
    unsigned long long d;
    asm("mov.b64 %0, {%1, %1};" : "=l"(d) : "r"(__float_as_uint(s)));
    return d;
}
__device__ __forceinline__ void fma2(unsigned long long& d,
                                     unsigned long long a, unsigned long long b) {
    asm("fma.rn.f32x2 %0, %1, %2, %0;" : "+l"(d) : "l"(a), "l"(b));
}

#define FMA2_ROW(J, WS)                                   \
    do {                                                  \
        const unsigned long long wdup = dup2(WS);         \
        fma2(acc[J][0], wdup, xa.x);                      \
        fma2(acc[J][1], wdup, xa.y);                      \
        fma2(acc[J][2], wdup, xb.x);                      \
        fma2(acc[J][3], wdup, xb.y);                      \
    } while (0)

__global__ __launch_bounds__(NT, 3)
void gnn_fused(const float* __restrict__ x,
               const float* __restrict__ w0, const float* __restrict__ w1,
               const float* __restrict__ w2, const float* __restrict__ w3,
               const float* __restrict__ aw0, const float* __restrict__ aw1,
               const float* __restrict__ aw2, const float* __restrict__ aw3,
               const float* __restrict__ b0, const float* __restrict__ b1,
               const float* __restrict__ b2, const float* __restrict__ b3,
               float* __restrict__ out, int B)
{
    extern __shared__ float smem[];
    float* S0   = smem;              // half 0: batches 0..3, rows rofs()
    float* S1   = S0 + HALF;         // half 1: batches 4..7
    float* X0   = S1 + HALF;         // xin halves (same row map, FIN rows)
    float* X1   = X0 + XHALF;
    float* aeff = X1 + XHALF;        // 4*70
    float* bias = aeff + 280;        // 3*64 + 13

    const int tid = threadIdx.x;
    const long brow0 = (long)blockIdx.x * TB;

    // ---- stage constants ----
    for (int idx = tid; idx < 4 * 70; idx += NT) {
        int l = idx / 70, e = idx - l * 70;
        const float* aw = (l == 0) ? aw0 : (l == 1) ? aw1 : (l == 2) ? aw2 : aw3;
        aeff[idx] = aw[c_nbr_m[e] * NN + c_nbr_lst[e]];
    }
    for (int idx = tid; idx < 3 * WD + FOUT; idx += NT) {
        float v;
        if      (idx <     WD) v = b0[idx];
        else if (idx < 2 * WD) v = b1[idx - WD];
        else if (idx < 3 * WD) v = b2[idx - 2 * WD];
        else                   v = b3[idx - 3 * WD];
        bias[idx] = v;
    }
    // ---- stage input transposed to [half][row=n*7+i][b] with root mask ----
    for (int e = tid; e < TB * ROWS_X; e += NT) {
        const int bl = e / ROWS_X;         // batch row 0..7
        const int j  = e - bl * ROWS_X;    // n*7+i
        float v = 0.0f;
        if (brow0 + bl < B && j >= FIN)
            v = x[(brow0 + bl) * ROWS_X + j];
        float* Xh = (bl & 4) ? X1 : X0;
        Xh[rofs(j) + (bl & 3)] = v;
    }
    __syncthreads();

    const int n  = tid >> 4;         // node 0..23 (one node per 16 lanes)
    const int q  = tid & 15;
    const int o0 = q * 4;            // mm phases: output quad
    const int ih = q >> 1;           // agg phases: i stripe 0..7
    const int bh = q & 1;            // agg phases: batch half

    // ---- Layer 0: acc[j][bp] = sum_i w0[n][i][o0+j] * x[n][i][pair bp] ----
    {
        unsigned long long acc[4][4];
        #pragma unroll
        for (int j = 0; j < 4; j++)
            #pragma unroll
            for (int p = 0; p < 4; p++) acc[j][p] = 0ull;
        #pragma unroll
        for (int i = 0; i < FIN; i++) {
            const int r = n * FIN + i;
            const float4 wv = __ldg(reinterpret_cast<const float4*>(w0 + r * WD + o0));
            const ulonglong2 xa = *reinterpret_cast<const ulonglong2*>(X0 + rofs(r));
            const ulonglong2 xb = *reinterpret_cast<const ulonglong2*>(X1 + rofs(r));
            FMA2_ROW(0, wv.x);
            FMA2_ROW(1, wv.y);
            FMA2_ROW(2, wv.z);
            FMA2_ROW(3, wv.w);
        }
        #pragma unroll
        for (int j = 0; j < 4; j++) {
            const int r = n * WD + o0 + j;
            *reinterpret_cast<ulonglong2*>(S0 + rofs(r)) = make_ulonglong2(acc[j][0], acc[j][1]);
            *reinterpret_cast<ulonglong2*>(S1 + rofs(r)) = make_ulonglong2(acc[j][2], acc[j][3]);
        }
    }
    __syncthreads();

    // ---- In-place tree aggregation + bias + ReLU on S (thread = n, ih, bh) ----
    auto agg = [&](const float* __restrict__ ae, const float* __restrict__ bi) {
        const int s = c_nbr_off[n], e = c_nbr_off[n + 1];
        float* Sh = bh ? S1 : S0;
        float4 a[8];
        #pragma unroll
        for (int k = 0; k < 8; k++) {
            const float v = bi[ih + 8 * k];
            a[k] = make_float4(v, v, v, v);
        }
        for (int kk = s; kk < e; kk++) {
            const float aw = ae[kk];
            const int nb = c_nbr_lst[kk];
            #pragma unroll
            for (int k = 0; k < 8; k++) {
                const float4 h = *reinterpret_cast<const float4*>(Sh + rofs(nb * WD + ih + 8 * k));
                a[k].x = fmaf(aw, h.x, a[k].x);
                a[k].y = fmaf(aw, h.y, a[k].y);
                a[k].z = fmaf(aw, h.z, a[k].z);
                a[k].w = fmaf(aw, h.w, a[k].w);
            }
        }
        __syncthreads();    // all reads complete before in-place writes
        #pragma unroll
        for (int k = 0; k < 8; k++) {
            a[k].x = fmaxf(a[k].x, 0.f); a[k].y = fmaxf(a[k].y, 0.f);
            a[k].z = fmaxf(a[k].z, 0.f); a[k].w = fmaxf(a[k].w, 0.f);
            *reinterpret_cast<float4*>(Sh + rofs(n * WD + ih + 8 * k)) = a[k];
        }
        __syncthreads();
    };

    // ---- In-place hidden matmul, b-packed f32x2 ----
    auto mm64 = [&](const float* __restrict__ wgt) {
        unsigned long long acc[4][4];
        #pragma unroll
        for (int j = 0; j < 4; j++)
            #pragma unroll
            for (int p = 0; p < 4; p++) acc[j][p] = 0ull;
        const float* wrow = wgt + n * WD * WD + o0;
        const int rbase = n * WD;
        #pragma unroll 4
        for (int i = 0; i < WD; i++) {
            const float4 wv = __ldg(reinterpret_cast<const float4*>(wrow + i * WD));
            const ulonglong2 xa = *reinterpret_cast<const ulonglong2*>(S0 + rofs(rbase + i));
            const ulonglong2 xb = *reinterpret_cast<const ulonglong2*>(S1 + rofs(rbase + i));
            FMA2_ROW(0, wv.x);
            FMA2_ROW(1, wv.y);
            FMA2_ROW(2, wv.z);
            FMA2_ROW(3, wv.w);
        }
        __syncthreads();    // all reads of S complete CTA-wide
        #pragma unroll
        for (int j = 0; j < 4; j++) {
            const int r = n * WD + o0 + j;
            *reinterpret_cast<ulonglong2*>(S0 + rofs(r)) = make_ulonglong2(acc[j][0], acc[j][1]);
            *reinterpret_cast<ulonglong2*>(S1 + rofs(r)) = make_ulonglong2(acc[j][2], acc[j][3]);
        }
        __syncthreads();
    };

    agg(aeff + 0,   bias + 0);        // L0 agg (+relu)
    mm64(w1);                          // L1 matmul
    agg(aeff + 70,  bias + WD);       // L1 agg (+relu)
    mm64(w2);                          // L2 matmul
    agg(aeff + 140, bias + 2 * WD);   // L2 agg (+relu)

    // ---- Layer 3 matmul: S @ w3 -> regs -> S head rows (n3*13+o3) ----
    const bool l3act = (tid < NN * FOUT);
    int n3 = 0, o3 = 0;
    float4 a0 = make_float4(0.f, 0.f, 0.f, 0.f);
    float4 a1 = a0;
    if (l3act) {
        n3 = tid / FOUT; o3 = tid - n3 * FOUT;
        #pragma unroll 4
        for (int i = 0; i < WD; i++) {
            const float wv = __ldg(w3 + (n3 * WD + i) * FOUT + o3);
            const int r = n3 * WD + i;
            const float4 h0 = *reinterpret_cast<const float4*>(S0 + rofs(r));
            const float4 h1 = *reinterpret_cast<const float4*>(S1 + rofs(r));
            a0.x = fmaf(wv, h0.x, a0.x); a0.y = fmaf(wv, h0.y, a0.y);
            a0.z = fmaf(wv, h0.z, a0.z); a0.w = fmaf(wv, h0.w, a0.w);
            a1.x = fmaf(wv, h1.x, a1.x); a1.y = fmaf(wv, h1.y, a1.y);
            a1.z = fmaf(wv, h1.z, a1.z); a1.w = fmaf(wv, h1.w, a1.w);
        }
    }
    __syncthreads();     // all L3 reads of S done before head overwrite
    if (l3act) {
        const int rb = n3 * FOUT + o3;   // = tid
        *reinterpret_cast<float4*>(S0 + rofs(rb)) = a0;
        *reinterpret_cast<float4*>(S1 + rofs(rb)) = a1;
    }
    __syncthreads();

    // ---- Final aggregation + bias, store to global ----
    if (l3act) {
        const int s = c_nbr_off[n3], e = c_nbr_off[n3 + 1];
        const float bv = bias[3 * WD + o3];
        float4 r0 = make_float4(bv, bv, bv, bv);
        float4 r1 = r0;
        for (int kk = s; kk < e; kk++) {
            const float aw = aeff[210 + kk];
            const int rb = c_nbr_lst[kk] * FOUT + o3;
            const float4 h0 = *reinterpret_cast<const float4*>(S0 + rofs(rb));
            const float4 h1 = *reinterpret_cast<const float4*>(S1 + rofs(rb));
            r0.x = fmaf(aw, h0.x, r0.x); r0.y = fmaf(aw, h0.y, r0.y);
            r0.z = fmaf(aw, h0.z, r0.z); r0.w = fmaf(aw, h0.w, r0.w);
            r1.x = fmaf(aw, h1.x, r1.x); r1.y = fmaf(aw, h1.y, r1.y);
            r1.z = fmaf(aw, h1.z, r1.z); r1.w = fmaf(aw, h1.w, r1.w);
        }
        const int col = n3 * FOUT + o3;  // = tid
        const float v0[4] = {r0.x, r0.y, r0.z, r0.w};
        const float v1[4] = {r1.x, r1.y, r1.z, r1.w};
        #pragma unroll
        for (int bi = 0; bi < 4; bi++) {
            if (brow0 + bi < B)
                out[(brow0 + bi) * (NN * FOUT) + col] = v0[bi];
            if (brow0 + 4 + bi < B)
                out[(brow0 + 4 + bi) * (NN * FOUT) + col] = v1[bi];
        }
    }
}

extern "C" void kernel_launch(void* const* d_in, const int* in_sizes, int n_in,
                              void* d_out, int out_size) {
    const float* x   = (const float*)d_in[0];
    const float* w0  = (const float*)d_in[1];
    const float* w1  = (const float*)d_in[2];
    const float* w2  = (const float*)d_in[3];
    const float* w3  = (const float*)d_in[4];
    const float* aw0 = (const float*)d_in[5];
    const float* aw1 = (const float*)d_in[6];
    const float* aw2 = (const float*)d_in[7];
    const float* aw3 = (const float*)d_in[8];
    const float* b0  = (const float*)d_in[9];
    const float* b1  = (const float*)d_in[10];
    const float* b2  = (const float*)d_in[11];
    const float* b3  = (const float*)d_in[12];
    float* out = (float*)d_out;

    const int B = in_sizes[0] / (NN * FIN);
    const int grid = (B + TB - 1) / TB;
    const size_t smem_bytes =
        (size_t)(2 * HALF + 2 * XHALF + 280 + 3 * WD + FOUT) * sizeof(float);

    cudaFuncSetAttribute(gnn_fused, cudaFuncAttributeMaxDynamicSharedMemorySize,
                         (int)smem_bytes);
    gnn_fused<<<grid, NT, smem_bytes>>>(x, w0, w1, w2, w3,
                                        aw0, aw1, aw2, aw3,
                                        b0, b1, b2, b3, out, B);
}